// round 14
// baseline (speedup 1.0000x reference)
#include <cuda_runtime.h>

#define TT 512
#define BB 128
#define EE 128
#define HH 256
#define MM 1024
#define CC 5

// Scratch (static device globals — no allocation allowed).
// xproj padded by 512 floats so the per-step prefetch can read one row past the end.
__device__ float g_xproj[BB * TT * HH + 512];
__device__ float g_hn[BB * HH];
__device__ float g_relu1[BB * MM];

// ---------------------------------------------------------------------------
// f32x2 packed-FMA helpers (Blackwell FFMA2 path; ptxas won't auto-fuse)
// ---------------------------------------------------------------------------
__device__ __forceinline__ void fma2(unsigned long long& acc,
                                     unsigned long long a,
                                     unsigned long long b) {
    asm("fma.rn.f32x2 %0, %1, %2, %0;" : "+l"(acc) : "l"(a), "l"(b));
}
__device__ __forceinline__ float red2(unsigned long long a) {
    float lo, hi;
    asm("mov.b64 {%0, %1}, %2;" : "=f"(lo), "=f"(hi) : "l"(a));
    return lo + hi;
}
__device__ __forceinline__ float tanh_fast(float x) {
    // (e^{2x}-1)/(e^{2x}+1), clamped so __expf never overflows. abs err ~1e-6.
    float xc = fminf(fmaxf(x, -9.0f), 9.0f);
    float e = __expf(2.0f * xc);
    return __fdividef(e - 1.0f, e + 1.0f);
}

// ---------------------------------------------------------------------------
// Kernel 1: xproj[b,t,j] = emb[x[b,t]] . W_ih[j,:] + b_ih[j] + b_hh[j]
// grid (8 t-tiles of 64, 128 b), 256 thr. Fully-inactive tiles early-exit.
// Thread tile: 8 tokens x 8 j. W smem stride 132 (=4 mod 32): conflict-free.
// (Exact R10 version — known good.)
// ---------------------------------------------------------------------------
__global__ void __launch_bounds__(256, 1) k_xproj(
    const int* __restrict__ x, const int* __restrict__ lengths,
    const float* __restrict__ emb, const float* __restrict__ W_ih,
    const float* __restrict__ b_ih, const float* __restrict__ b_hh)
{
    int b = blockIdx.y;
    int t_base = blockIdx.x * 64;
    int t0 = TT - lengths[b];
    if (t_base + 64 <= t0) return;  // tile entirely before this sequence starts

    extern __shared__ float sm1[];
    float* Ws = sm1;                  // [256][132]
    float* Es = sm1 + 256 * 132;      // [64][132]
    int*   ids = (int*)(Es + 64 * 132);

    int tid = threadIdx.x;
    if (tid < 64) ids[tid] = x[b * TT + t_base + tid];
    for (int idx = tid; idx < 256 * 32; idx += 256) {
        int r = idx >> 5, c4 = idx & 31;
        *(float4*)&Ws[r * 132 + c4 * 4] = *(const float4*)&W_ih[r * EE + c4 * 4];
    }
    __syncthreads();
    for (int idx = tid; idx < 64 * 32; idx += 256) {
        int r = idx >> 5, c4 = idx & 31;
        *(float4*)&Es[r * 132 + c4 * 4] = *(const float4*)&emb[ids[r] * EE + c4 * 4];
    }
    __syncthreads();

    int u = tid & 31;   // lane -> j = u + 32*jj (consecutive lanes, conflict-free W)
    int v = tid >> 5;   // warp -> tokens v*8 .. v*8+7 (broadcast E reads)

    unsigned long long acc[8][8];
    #pragma unroll
    for (int i = 0; i < 8; i++)
        #pragma unroll
        for (int jj = 0; jj < 8; jj++) acc[i][jj] = 0ULL;

    #pragma unroll 1
    for (int k4 = 0; k4 < 32; ++k4) {
        ulonglong2 w[8];
        #pragma unroll
        for (int jj = 0; jj < 8; jj++)
            w[jj] = *(const ulonglong2*)&Ws[(u + 32 * jj) * 132 + k4 * 4];
        #pragma unroll
        for (int i = 0; i < 8; i++) {
            ulonglong2 a = *(const ulonglong2*)&Es[(v * 8 + i) * 132 + k4 * 4];
            #pragma unroll
            for (int jj = 0; jj < 8; jj++) fma2(acc[i][jj], a.x, w[jj].x);
            #pragma unroll
            for (int jj = 0; jj < 8; jj++) fma2(acc[i][jj], a.y, w[jj].y);
        }
    }

    float bsum[8];
    #pragma unroll
    for (int jj = 0; jj < 8; jj++) {
        int j = u + 32 * jj;
        bsum[jj] = b_ih[j] + b_hh[j];
    }
    #pragma unroll
    for (int i = 0; i < 8; i++) {
        int t = t_base + v * 8 + i;
        float* dst = &g_xproj[(b * TT + t) * HH];
        #pragma unroll
        for (int jj = 0; jj < 8; jj++)
            dst[u + 32 * jj] = red2(acc[i][jj]) + bsum[jj];  // coalesced 128B/warp
    }
}

// ---------------------------------------------------------------------------
// Kernel 2: recurrence, k-sliced (R10 structure), W-in-regs 24 -> 26 cols.
// One CTA per batch, 256 threads = 8 warps. Warp ks owns k-slice
// [32ks, 32ks+32): reads only h[32ks..32ks+32) (8 broadcast LDS.128).
// Lane owns 8 outputs j = l + 32*o. Per output: k-cols [32ks, 32ks+26)
// in registers (13 ull x 8 outputs = 208 regs), cols [32ks+26, 32ks+32)
// in smem (3 x LDS.64, row stride 54: 54 = 2 mod 4 -> the two 16-lane
// LDS.64 phases hit 16 distinct bank-pairs each, conflict-free).
// Partials -> psum[8][264]; thread j reduces, adds xproj, tanh, writes h.
// Two barriers per step (the R10-proven structure).
// ---------------------------------------------------------------------------
__global__ void __launch_bounds__(256, 1) k_rnn(
    const float* __restrict__ W_hh, const int* __restrict__ lengths)
{
    extern __shared__ float sm2[];
    float* Wsh  = sm2;               // [256][54]: row j, slice s cols [32s+26,32s+32) at +6s
    float* psum = sm2 + 256 * 54;    // [8][264] (stride 264 = 8 mod 32)
    float* hbuf = psum + 8 * 264;    // [264], 16B-aligned

    int b = blockIdx.x;
    int tid = threadIdx.x;
    int ks = tid >> 5;               // warp = k-slice
    int l = tid & 31;

    // W register part: 8 outputs (j = l + 32o), 13 ull (26 k-cols) each
    unsigned long long WR[104];
    #pragma unroll
    for (int o = 0; o < 8; o++) {
        const unsigned long long* src =
            (const unsigned long long*)(W_hh + (l + 32 * o) * HH + ks * 32);
        #pragma unroll
        for (int p = 0; p < 13; p++) WR[o * 13 + p] = src[p];
    }
    // smem W fill: row r, slice s, cols [32s+26, 32s+32) -> Wsh[r*54 + 6s ..]
    for (int idx = tid; idx < 256 * 48; idx += 256) {
        int r = idx / 48, f = idx % 48;   // f = 6s + c
        int s = f / 6, c = f % 6;
        Wsh[r * 54 + f] = W_hh[r * HH + s * 32 + 26 + c];
    }
    hbuf[tid] = 0.0f;
    __syncthreads();

    int len = lengths[b];
    float hfin = 0.0f;
    if (len > 0) {
        int t0 = TT - len;
        const float* xp = g_xproj + (b * TT + t0) * HH + tid;
        float xv = *xp;                                   // xproj for first step
        const ulonglong2* hs = (const ulonglong2*)(hbuf + ks * 32);
        const float* wsp = Wsh + l * 54 + ks * 6;
        float* ps = psum + ks * 264 + l;
        const float* rp = psum + tid;
        for (int t = t0; t < TT; ++t) {
            unsigned long long acc[8];
            #pragma unroll
            for (int o = 0; o < 8; o++) acc[o] = 0ULL;
            // k-pairs 0..11 of this slice: W from registers, h broadcast LDS
            #pragma unroll
            for (int c = 0; c < 6; c++) {
                ulonglong2 hv = hs[c];
                #pragma unroll
                for (int o = 0; o < 8; o++) {
                    fma2(acc[o], hv.x, WR[o * 13 + 2 * c]);
                    fma2(acc[o], hv.y, WR[o * 13 + 2 * c + 1]);
                }
            }
            // k-pairs 12..15: pair 12 from registers; pairs 13..15 from smem
            {
                ulonglong2 h6 = hs[6], h7 = hs[7];
                #pragma unroll
                for (int o = 0; o < 8; o++) {
                    const unsigned long long* wb =
                        (const unsigned long long*)(wsp + o * (32 * 54));
                    fma2(acc[o], h6.x, WR[o * 13 + 12]);
                    fma2(acc[o], h6.y, wb[0]);
                    fma2(acc[o], h7.x, wb[1]);
                    fma2(acc[o], h7.y, wb[2]);
                }
            }
            // publish slice partials (coalesced STS.32)
            #pragma unroll
            for (int o = 0; o < 8; o++) ps[o * 32] = red2(acc[o]);
            __syncthreads();
            // reduce: thread j = tid sums 8 slice partials + xproj
            float xc = xv;
            xv = xp[HH];                                  // prefetch (padded array)
            float p0 = rp[0 * 264], p1 = rp[1 * 264];
            float p2 = rp[2 * 264], p3 = rp[3 * 264];
            float p4 = rp[4 * 264], p5 = rp[5 * 264];
            float p6 = rp[6 * 264], p7 = rp[7 * 264];
            float sv = xc + (((p0 + p1) + (p2 + p3)) + ((p4 + p5) + (p6 + p7)));
            hfin = tanh_fast(sv);
            hbuf[tid] = hfin;
            __syncthreads();
            xp += HH;
        }
    }
    g_hn[b * HH + tid] = hfin;
}

// ---------------------------------------------------------------------------
// Kernel 3: relu(hn @ W0^T + b0). 32 CTAs = 8 b-groups(16) x 4 m-tiles(256);
// W0 traffic amortized over 16 batches (8 MB total).
// ---------------------------------------------------------------------------
__global__ void __launch_bounds__(256, 1) k_mlp1(
    const float* __restrict__ W0, const float* __restrict__ b0)
{
    __shared__ float hs[16 * 256];
    int tid = threadIdx.x;
    int bg = blockIdx.x & 7, mt = blockIdx.x >> 3;
    for (int idx = tid; idx < 16 * 64; idx += 256) {
        int r = idx >> 6, c4 = idx & 63;
        *(float4*)&hs[r * 256 + c4 * 4] =
            *(const float4*)&g_hn[(bg * 16 + r) * HH + c4 * 4];
    }
    __syncthreads();
    int m = mt * 256 + tid;
    unsigned long long accA[16], accB[16];
    #pragma unroll
    for (int r = 0; r < 16; r++) { accA[r] = 0ULL; accB[r] = 0ULL; }
    const float* wrow = W0 + m * HH;
    #pragma unroll 4
    for (int k4 = 0; k4 < 64; k4++) {
        ulonglong2 w = *(const ulonglong2*)&wrow[k4 * 4];
        #pragma unroll
        for (int r = 0; r < 16; r++) {
            ulonglong2 a = *(const ulonglong2*)&hs[r * 256 + k4 * 4];
            fma2(accA[r], a.x, w.x);
            fma2(accB[r], a.y, w.y);
        }
    }
    float bm = b0[m];
    #pragma unroll
    for (int r = 0; r < 16; r++) {
        float s = red2(accA[r]) + red2(accB[r]) + bm;
        g_relu1[(bg * 16 + r) * MM + m] = fmaxf(s, 0.0f);
    }
}

// ---------------------------------------------------------------------------
// Kernel 4: relu(h @ W1^T + b1) then log_softmax over C=5. 1 CTA/batch,
// 5 warps (one per class), warp-shuffle reduction.
// ---------------------------------------------------------------------------
__global__ void k_head(const float* __restrict__ W1, const float* __restrict__ b1,
                       float* __restrict__ out)
{
    __shared__ float logit[8];
    int b = blockIdx.x;
    int tid = threadIdx.x;            // 160 threads = 5 warps
    int c = tid >> 5, lane = tid & 31;
    const float* hr = g_relu1 + b * MM;
    const float* wr = W1 + c * MM;
    float acc = 0.0f;
    for (int k = lane * 4; k < MM; k += 128) {
        float4 a = *(const float4*)&hr[k];
        float4 w = *(const float4*)&wr[k];
        acc += a.x * w.x + a.y * w.y;
        acc += a.z * w.z + a.w * w.w;
    }
    #pragma unroll
    for (int o = 16; o; o >>= 1) acc += __shfl_xor_sync(0xffffffffu, acc, o);
    if (lane == 0) logit[c] = fmaxf(acc + b1[c], 0.0f);
    __syncthreads();
    if (tid < CC) {
        float mx = logit[0];
        #pragma unroll
        for (int i = 1; i < CC; i++) mx = fmaxf(mx, logit[i]);
        float se = 0.0f;
        #pragma unroll
        for (int i = 0; i < CC; i++) se += __expf(logit[i] - mx);
        out[b * CC + tid] = logit[tid] - mx - logf(se);
    }
}

// ---------------------------------------------------------------------------
extern "C" void kernel_launch(void* const* d_in, const int* in_sizes, int n_in,
                              void* d_out, int out_size)
{
    const int*   x    = (const int*)  d_in[0];
    const int*   len  = (const int*)  d_in[1];
    const float* emb  = (const float*)d_in[2];
    const float* W_ih = (const float*)d_in[3];
    const float* W_hh = (const float*)d_in[4];
    const float* b_ih = (const float*)d_in[5];
    const float* b_hh = (const float*)d_in[6];
    const float* W0   = (const float*)d_in[7];
    const float* b0   = (const float*)d_in[8];
    const float* W1   = (const float*)d_in[9];
    const float* b1   = (const float*)d_in[10];
    float* out = (float*)d_out;

    const int smem1 = (256 * 132 + 64 * 132) * 4 + 64 * 4;        // 169,216 B
    const int smem2 = (256 * 54 + 8 * 264 + 264) * 4;             //  64,800 B
    cudaFuncSetAttribute(k_xproj, cudaFuncAttributeMaxDynamicSharedMemorySize, smem1);
    cudaFuncSetAttribute(k_rnn,   cudaFuncAttributeMaxDynamicSharedMemorySize, smem2);

    k_xproj<<<dim3(8, 128), 256, smem1>>>(x, len, emb, W_ih, b_ih, b_hh);
    k_rnn<<<128, 256, smem2>>>(W_hh, len);
    k_mlp1<<<32, 256>>>(W0, b0);
    k_head<<<128, 160>>>(W1, b1, out);
}

// round 16
// speedup vs baseline: 1.0124x; 1.0124x over previous
#include <cuda_runtime.h>

#define TT 512
#define BB 128
#define EE 128
#define HH 256
#define MM 1024
#define CC 5

// Scratch (static device globals — no allocation allowed).
// xproj padded by 512 floats so the per-step prefetch can read one row past the end.
__device__ float g_xproj[BB * TT * HH + 512];
__device__ float g_hn[BB * HH];
__device__ float g_relu1[BB * MM];

// ---------------------------------------------------------------------------
// f32x2 packed-FMA helpers (Blackwell FFMA2 path; ptxas won't auto-fuse)
// ---------------------------------------------------------------------------
__device__ __forceinline__ void fma2(unsigned long long& acc,
                                     unsigned long long a,
                                     unsigned long long b) {
    asm("fma.rn.f32x2 %0, %1, %2, %0;" : "+l"(acc) : "l"(a), "l"(b));
}
__device__ __forceinline__ float red2(unsigned long long a) {
    float lo, hi;
    asm("mov.b64 {%0, %1}, %2;" : "=f"(lo), "=f"(hi) : "l"(a));
    return lo + hi;
}
__device__ __forceinline__ float tanh_fast(float x) {
    // (e^{2x}-1)/(e^{2x}+1), clamped so __expf never overflows. abs err ~1e-6.
    float xc = fminf(fmaxf(x, -9.0f), 9.0f);
    float e = __expf(2.0f * xc);
    return __fdividef(e - 1.0f, e + 1.0f);
}

// Empty dummy kernel: shifts ncu's capture slot so (hopefully) k_rnn lands in
// the profiled launch index next round. Deterministic, does no work.
__global__ void k_nop() {}

// ---------------------------------------------------------------------------
// Kernel 1: xproj[b,t,j] = emb[x[b,t]] . W_ih[j,:] + b_ih[j] + b_hh[j]
// grid (8 t-tiles of 64, 128 b), 256 thr. Fully-inactive tiles early-exit.
// Thread tile: 8 tokens x 8 j. W smem stride 132 (=4 mod 32): conflict-free.
// (Exact R10 version — known good.)
// ---------------------------------------------------------------------------
__global__ void __launch_bounds__(256, 1) k_xproj(
    const int* __restrict__ x, const int* __restrict__ lengths,
    const float* __restrict__ emb, const float* __restrict__ W_ih,
    const float* __restrict__ b_ih, const float* __restrict__ b_hh)
{
    int b = blockIdx.y;
    int t_base = blockIdx.x * 64;
    int t0 = TT - lengths[b];
    if (t_base + 64 <= t0) return;  // tile entirely before this sequence starts

    extern __shared__ float sm1[];
    float* Ws = sm1;                  // [256][132]
    float* Es = sm1 + 256 * 132;      // [64][132]
    int*   ids = (int*)(Es + 64 * 132);

    int tid = threadIdx.x;
    if (tid < 64) ids[tid] = x[b * TT + t_base + tid];
    for (int idx = tid; idx < 256 * 32; idx += 256) {
        int r = idx >> 5, c4 = idx & 31;
        *(float4*)&Ws[r * 132 + c4 * 4] = *(const float4*)&W_ih[r * EE + c4 * 4];
    }
    __syncthreads();
    for (int idx = tid; idx < 64 * 32; idx += 256) {
        int r = idx >> 5, c4 = idx & 31;
        *(float4*)&Es[r * 132 + c4 * 4] = *(const float4*)&emb[ids[r] * EE + c4 * 4];
    }
    __syncthreads();

    int u = tid & 31;   // lane -> j = u + 32*jj (consecutive lanes, conflict-free W)
    int v = tid >> 5;   // warp -> tokens v*8 .. v*8+7 (broadcast E reads)

    unsigned long long acc[8][8];
    #pragma unroll
    for (int i = 0; i < 8; i++)
        #pragma unroll
        for (int jj = 0; jj < 8; jj++) acc[i][jj] = 0ULL;

    #pragma unroll 1
    for (int k4 = 0; k4 < 32; ++k4) {
        ulonglong2 w[8];
        #pragma unroll
        for (int jj = 0; jj < 8; jj++)
            w[jj] = *(const ulonglong2*)&Ws[(u + 32 * jj) * 132 + k4 * 4];
        #pragma unroll
        for (int i = 0; i < 8; i++) {
            ulonglong2 a = *(const ulonglong2*)&Es[(v * 8 + i) * 132 + k4 * 4];
            #pragma unroll
            for (int jj = 0; jj < 8; jj++) fma2(acc[i][jj], a.x, w[jj].x);
            #pragma unroll
            for (int jj = 0; jj < 8; jj++) fma2(acc[i][jj], a.y, w[jj].y);
        }
    }

    float bsum[8];
    #pragma unroll
    for (int jj = 0; jj < 8; jj++) {
        int j = u + 32 * jj;
        bsum[jj] = b_ih[j] + b_hh[j];
    }
    #pragma unroll
    for (int i = 0; i < 8; i++) {
        int t = t_base + v * 8 + i;
        float* dst = &g_xproj[(b * TT + t) * HH];
        #pragma unroll
        for (int jj = 0; jj < 8; jj++)
            dst[u + 32 * jj] = red2(acc[i][jj]) + bsum[jj];  // coalesced 128B/warp
    }
}

// ---------------------------------------------------------------------------
// Kernel 2: recurrence, k-sliced (R10 layout, 24 W-cols in regs), with the
// second barrier removed. Key invariant of this layout: warp ks writes
// h[32ks..32ks+32) and is the ONLY reader of that range -> h is warp-local,
// so the h publish needs only __syncwarp. psum is double-buffered by step
// parity so a fast warp's step-(t+1) partials can't clobber step-t values a
// slow warp is still reading. ONE __syncthreads per step.
// Per output: k-cols [32ks,32ks+24) in regs (12 ull x 8 outputs = 192 regs),
// cols [32ks+24,32ks+32) in smem (2 conflict-free LDS.128, stride 68).
// ---------------------------------------------------------------------------
__global__ void __launch_bounds__(256, 1) k_rnn(
    const float* __restrict__ W_hh, const int* __restrict__ lengths)
{
    extern __shared__ float sm2[];
    float* Wsh  = sm2;                // [256][68]: row j, slice s cols [32s+24,32s+32) at +8s
    float* psum = sm2 + 256 * 68;     // [2][8][264] parity-double-buffered (stride 264 = 8 mod 32)
    float* hbuf = psum + 2 * 8 * 264; // [264], 16B-aligned; warp-local access only

    int b = blockIdx.x;
    int tid = threadIdx.x;
    int ks = tid >> 5;               // warp = k-slice = h-slice
    int l = tid & 31;

    // W register part: 8 outputs (j = l + 32o), 12 ull (24 k-cols) each
    unsigned long long WR[96];
    #pragma unroll
    for (int o = 0; o < 8; o++) {
        const unsigned long long* src =
            (const unsigned long long*)(W_hh + (l + 32 * o) * HH + ks * 32);
        #pragma unroll
        for (int p = 0; p < 12; p++) WR[o * 12 + p] = src[p];
    }
    // smem W fill: row r, slice s, cols [32s+24, 32s+32) -> Wsh[r*68 + 8s ..]
    for (int idx = tid; idx < 256 * 16; idx += 256) {
        int r = idx >> 4, f = idx & 15;   // f = 2s + q
        int s = f >> 1, q = f & 1;
        *(float4*)&Wsh[r * 68 + f * 4] =
            *(const float4*)&W_hh[r * HH + s * 32 + 24 + q * 4];
    }
    hbuf[tid] = 0.0f;
    __syncthreads();

    int len = lengths[b];
    float hfin = 0.0f;
    if (len > 0) {
        int t0 = TT - len;
        const float* xp = g_xproj + (b * TT + t0) * HH + tid;
        float xv = *xp;                                   // xproj for first step
        const ulonglong2* hs = (const ulonglong2*)(hbuf + ks * 32);
        const float* wsp = Wsh + l * 68 + ks * 8;
        for (int t = t0; t < TT; ++t) {
            float* pb = psum + (t & 1) * (8 * 264);       // this step's psum buffer
            unsigned long long acc[8];
            #pragma unroll
            for (int o = 0; o < 8; o++) acc[o] = 0ULL;
            // k-pairs 0..11 of this slice: W from registers, h broadcast LDS
            #pragma unroll
            for (int c = 0; c < 6; c++) {
                ulonglong2 hv = hs[c];
                #pragma unroll
                for (int o = 0; o < 8; o++) {
                    fma2(acc[o], hv.x, WR[o * 12 + 2 * c]);
                    fma2(acc[o], hv.y, WR[o * 12 + 2 * c + 1]);
                }
            }
            // k-pairs 12..15: W from smem (2 LDS.128 per output)
            {
                ulonglong2 h6 = hs[6], h7 = hs[7];
                #pragma unroll
                for (int o = 0; o < 8; o++) {
                    ulonglong2 w0 = *(const ulonglong2*)(wsp + o * (32 * 68));
                    ulonglong2 w1 = *(const ulonglong2*)(wsp + o * (32 * 68) + 4);
                    fma2(acc[o], h6.x, w0.x); fma2(acc[o], h6.y, w0.y);
                    fma2(acc[o], h7.x, w1.x); fma2(acc[o], h7.y, w1.y);
                }
            }
            // publish slice partials (coalesced STS.32)
            {
                float* ps = pb + ks * 264 + l;
                #pragma unroll
                for (int o = 0; o < 8; o++) ps[o * 32] = red2(acc[o]);
            }
            __syncthreads();                              // the ONLY barrier
            // reduce: thread j = tid sums 8 slice partials + xproj; h is
            // warp-local (warp ks both writes and reads h[32ks..32ks+32))
            {
                const float* rp = pb + tid;
                float xc = xv;
                xv = xp[HH];                              // prefetch (padded array)
                float p0 = rp[0 * 264], p1 = rp[1 * 264];
                float p2 = rp[2 * 264], p3 = rp[3 * 264];
                float p4 = rp[4 * 264], p5 = rp[5 * 264];
                float p6 = rp[6 * 264], p7 = rp[7 * 264];
                float sv = xc + (((p0 + p1) + (p2 + p3)) + ((p4 + p5) + (p6 + p7)));
                hfin = tanh_fast(sv);
                hbuf[tid] = hfin;                         // own slice only
            }
            __syncwarp();                                 // h publish is warp-local
            xp += HH;
        }
    }
    g_hn[b * HH + tid] = hfin;
}

// ---------------------------------------------------------------------------
// Kernel 3: relu(hn @ W0^T + b0). 32 CTAs = 8 b-groups(16) x 4 m-tiles(256);
// W0 traffic amortized over 16 batches (8 MB total).
// ---------------------------------------------------------------------------
__global__ void __launch_bounds__(256, 1) k_mlp1(
    const float* __restrict__ W0, const float* __restrict__ b0)
{
    __shared__ float hs[16 * 256];
    int tid = threadIdx.x;
    int bg = blockIdx.x & 7, mt = blockIdx.x >> 3;
    for (int idx = tid; idx < 16 * 64; idx += 256) {
        int r = idx >> 6, c4 = idx & 63;
        *(float4*)&hs[r * 256 + c4 * 4] =
            *(const float4*)&g_hn[(bg * 16 + r) * HH + c4 * 4];
    }
    __syncthreads();
    int m = mt * 256 + tid;
    unsigned long long accA[16], accB[16];
    #pragma unroll
    for (int r = 0; r < 16; r++) { accA[r] = 0ULL; accB[r] = 0ULL; }
    const float* wrow = W0 + m * HH;
    #pragma unroll 4
    for (int k4 = 0; k4 < 64; k4++) {
        ulonglong2 w = *(const ulonglong2*)&wrow[k4 * 4];
        #pragma unroll
        for (int r = 0; r < 16; r++) {
            ulonglong2 a = *(const ulonglong2*)&hs[r * 256 + k4 * 4];
            fma2(accA[r], a.x, w.x);
            fma2(accB[r], a.y, w.y);
        }
    }
    float bm = b0[m];
    #pragma unroll
    for (int r = 0; r < 16; r++) {
        float s = red2(accA[r]) + red2(accB[r]) + bm;
        g_relu1[(bg * 16 + r) * MM + m] = fmaxf(s, 0.0f);
    }
}

// ---------------------------------------------------------------------------
// Kernel 4: relu(h @ W1^T + b1) then log_softmax over C=5. 1 CTA/batch,
// 5 warps (one per class), warp-shuffle reduction.
// ---------------------------------------------------------------------------
__global__ void k_head(const float* __restrict__ W1, const float* __restrict__ b1,
                       float* __restrict__ out)
{
    __shared__ float logit[8];
    int b = blockIdx.x;
    int tid = threadIdx.x;            // 160 threads = 5 warps
    int c = tid >> 5, lane = tid & 31;
    const float* hr = g_relu1 + b * MM;
    const float* wr = W1 + c * MM;
    float acc = 0.0f;
    for (int k = lane * 4; k < MM; k += 128) {
        float4 a = *(const float4*)&hr[k];
        float4 w = *(const float4*)&wr[k];
        acc += a.x * w.x + a.y * w.y;
        acc += a.z * w.z + a.w * w.w;
    }
    #pragma unroll
    for (int o = 16; o; o >>= 1) acc += __shfl_xor_sync(0xffffffffu, acc, o);
    if (lane == 0) logit[c] = fmaxf(acc + b1[c], 0.0f);
    __syncthreads();
    if (tid < CC) {
        float mx = logit[0];
        #pragma unroll
        for (int i = 1; i < CC; i++) mx = fmaxf(mx, logit[i]);
        float se = 0.0f;
        #pragma unroll
        for (int i = 0; i < CC; i++) se += __expf(logit[i] - mx);
        out[b * CC + tid] = logit[tid] - mx - logf(se);
    }
}

// ---------------------------------------------------------------------------
extern "C" void kernel_launch(void* const* d_in, const int* in_sizes, int n_in,
                              void* d_out, int out_size)
{
    const int*   x    = (const int*)  d_in[0];
    const int*   len  = (const int*)  d_in[1];
    const float* emb  = (const float*)d_in[2];
    const float* W_ih = (const float*)d_in[3];
    const float* W_hh = (const float*)d_in[4];
    const float* b_ih = (const float*)d_in[5];
    const float* b_hh = (const float*)d_in[6];
    const float* W0   = (const float*)d_in[7];
    const float* b0   = (const float*)d_in[8];
    const float* W1   = (const float*)d_in[9];
    const float* b1   = (const float*)d_in[10];
    float* out = (float*)d_out;

    const int smem1 = (256 * 132 + 64 * 132) * 4 + 64 * 4;        // 169,216 B
    const int smem2 = (256 * 68 + 2 * 8 * 264 + 264) * 4;         //  87,584 B
    cudaFuncSetAttribute(k_xproj, cudaFuncAttributeMaxDynamicSharedMemorySize, smem1);
    cudaFuncSetAttribute(k_rnn,   cudaFuncAttributeMaxDynamicSharedMemorySize, smem2);

    // Two dummy launches shift the ncu capture slot: if the profiler captures
    // absolute launch index 3 (previously k_head), it now lands on k_rnn.
    k_nop<<<1, 32>>>();
    k_nop<<<1, 32>>>();
    k_xproj<<<dim3(8, 128), 256, smem1>>>(x, len, emb, W_ih, b_ih, b_hh);
    k_rnn<<<128, 256, smem2>>>(W_hh, len);
    k_mlp1<<<32, 256>>>(W0, b0);
    k_head<<<128, 160>>>(W1, b1, out);
}